// round 2
// baseline (speedup 1.0000x reference)
#include <cuda_runtime.h>

#define TS       100
#define FDIM     64
#define HDIM     32
#define ESTRIDE  66            // row stride in floats: 66 -> (2t+k) bank pattern, float2-aligned
#define NTHREADS 256
#define NPAIR    (TS * (TS - 1) / 2)      // 4950
#define DEEP_N   (TS * HDIM)              // 3200
#define WIDE_OFF (DEEP_N + NPAIR)         // 8150
#define NBLK     25                       // 100 / 4 row-blocks
#define NTRI_BLK (NBLK * (NBLK + 1) / 2)  // 325 upper-tri block pairs (incl diagonal blocks)
#define NTASKS   (NTRI_BLK * 2)           // split each block over 2 k-halves -> 650

// ---------------- packed f32x2 helpers (Blackwell FFMA2 pipe) ----------------
__device__ __forceinline__ unsigned long long pack2(float lo, float hi) {
    unsigned long long r;
    asm("mov.b64 %0, {%1, %2};" : "=l"(r) : "f"(lo), "f"(hi));
    return r;
}
__device__ __forceinline__ unsigned long long splat2(float x) {
    unsigned long long r;
    asm("mov.b64 %0, {%1, %1};" : "=l"(r) : "f"(x));
    return r;
}
__device__ __forceinline__ void fma2(unsigned long long& d, unsigned long long a,
                                     unsigned long long b) {
    asm("fma.rn.f32x2 %0, %1, %2, %3;" : "=l"(d) : "l"(a), "l"(b), "l"(d));
}
__device__ __forceinline__ float hsum2(unsigned long long v) {
    float lo, hi;
    asm("mov.b64 {%0, %1}, %2;" : "=f"(lo), "=f"(hi) : "l"(v));
    return lo + hi;
}
__device__ __forceinline__ void unpack2(unsigned long long v, float& lo, float& hi) {
    asm("mov.b64 {%0, %1}, %2;" : "=f"(lo), "=f"(hi) : "l"(v));
}

__global__ __launch_bounds__(NTHREADS)
void deepfm_fused_kernel(const int* __restrict__ x,
                         const float* __restrict__ emb,
                         const float* __restrict__ w_deep,
                         const float* __restrict__ b_deep,
                         const float* __restrict__ w_ffn,
                         const float* __restrict__ b_ffn,
                         float* __restrict__ out)
{
    __shared__ __align__(16) float es[TS * ESTRIDE];   // 26.4 KB embedding tile
    __shared__ __align__(16) float wd[FDIM * HDIM];    // 8 KB deep weights
    __shared__ int   tok[TS];
    __shared__ float red[NTHREADS / 32];

    const int b   = blockIdx.x;
    const int tid = threadIdx.x;

    // ---- phase 0: tokens + w_deep into shared ----
    if (tid < TS) tok[tid] = x[b * TS + tid];
    for (int i = tid; i < (FDIM * HDIM) / 4; i += NTHREADS)
        ((float4*)wd)[i] = ((const float4*)w_deep)[i];
    __syncthreads();

    // ---- phase 1: gather e = emb[x[b]] into shared (float2 granularity) ----
    for (int idx = tid; idx < TS * (FDIM / 2); idx += NTHREADS) {
        const int row = idx >> 5;            // /32 float2 per row
        const int c   = idx & 31;
        const float2 v = *(const float2*)(emb + (long)tok[row] * FDIM + c * 2);
        *(float2*)(es + row * ESTRIDE + c * 2) = v;
    }
    __syncthreads();

    float acc = 0.f;

    // ---- wide term: sum e[t,f] * w_ffn[WIDE_OFF + t*64 + f] ----
    {
        const float* ww = w_ffn + WIDE_OFF;
        for (int idx = tid; idx < TS * FDIM; idx += NTHREADS) {
            const int t = idx >> 6, f = idx & 63;
            acc += es[t * ESTRIDE + f] * ww[idx];
        }
    }

    // ---- deep term: 25 t-blocks x 8 h-blocks = 200 tasks (threads 0..199) ----
    if (tid < NBLK * 8) {
        const int t0 = (tid >> 3) * 4;
        const int h0 = (tid & 7) * 4;
        unsigned long long a01[4] = {0, 0, 0, 0};
        unsigned long long a23[4] = {0, 0, 0, 0};
        #pragma unroll 4
        for (int k = 0; k < FDIM; ++k) {
            const float4 w4 = *(const float4*)(wd + k * HDIM + h0);
            const unsigned long long w01 = pack2(w4.x, w4.y);
            const unsigned long long w23 = pack2(w4.z, w4.w);
            #pragma unroll
            for (int i = 0; i < 4; ++i) {
                const unsigned long long ei = splat2(es[(t0 + i) * ESTRIDE + k]);
                fma2(a01[i], ei, w01);
                fma2(a23[i], ei, w23);
            }
        }
        const float4 bd = *(const float4*)(b_deep + h0);
        #pragma unroll
        for (int i = 0; i < 4; ++i) {
            float d0, d1, d2, d3;
            unpack2(a01[i], d0, d1);
            unpack2(a23[i], d2, d3);
            const float* wdf = w_ffn + (t0 + i) * HDIM + h0;
            acc += fmaxf(d0 + bd.x, 0.f) * wdf[0];
            acc += fmaxf(d1 + bd.y, 0.f) * wdf[1];
            acc += fmaxf(d2 + bd.z, 0.f) * wdf[2];
            acc += fmaxf(d3 + bd.w, 0.f) * wdf[3];
        }
    }

    // ---- fm term: upper-tri 4x4 pair blocks, each split into 2 k-halves ----
    {
        const float* wfm = w_ffn + DEEP_N;
        for (int task = tid; task < NTASKS; task += NTHREADS) {
            const int blk = task >> 1;
            const int k0  = (task & 1) * (FDIM / 2);
            // map blk -> (ib, jb) with ib <= jb over 25x25 upper triangle
            int ib = 0, rem = blk;
            while (rem >= NBLK - ib) { rem -= NBLK - ib; ++ib; }
            const int jb = ib + rem;
            const int i0 = ib * 4, j0 = jb * 4;

            unsigned long long pacc[16];
            #pragma unroll
            for (int p = 0; p < 16; ++p) pacc[p] = 0ull;

            #pragma unroll 4
            for (int k = k0; k < k0 + FDIM / 2; k += 2) {
                unsigned long long ai[4], aj[4];
                #pragma unroll
                for (int i = 0; i < 4; ++i)
                    ai[i] = *(const unsigned long long*)(es + (i0 + i) * ESTRIDE + k);
                #pragma unroll
                for (int j = 0; j < 4; ++j)
                    aj[j] = *(const unsigned long long*)(es + (j0 + j) * ESTRIDE + k);
                #pragma unroll
                for (int i = 0; i < 4; ++i)
                    #pragma unroll
                    for (int j = 0; j < 4; ++j)
                        fma2(pacc[i * 4 + j], ai[i], aj[j]);
            }

            #pragma unroll
            for (int i = 0; i < 4; ++i) {
                const int gi = i0 + i;
                #pragma unroll
                for (int j = 0; j < 4; ++j) {
                    const int gj = j0 + j;
                    if (gi < gj) {
                        const int idx = gi * (2 * TS - gi - 1) / 2 + (gj - gi - 1);
                        acc += hsum2(pacc[i * 4 + j]) * wfm[idx];
                    }
                }
            }
        }
    }

    // ---- block reduce + sigmoid ----
    #pragma unroll
    for (int off = 16; off; off >>= 1)
        acc += __shfl_xor_sync(0xffffffffu, acc, off);
    if ((tid & 31) == 0) red[tid >> 5] = acc;
    __syncthreads();
    if (tid == 0) {
        float total = 0.f;
        #pragma unroll
        for (int w = 0; w < NTHREADS / 32; ++w) total += red[w];
        total += b_ffn[0];
        out[b] = 1.f / (1.f + expf(-total));
    }
}

extern "C" void kernel_launch(void* const* d_in, const int* in_sizes, int n_in,
                              void* d_out, int out_size) {
    const int*   x      = (const int*)d_in[0];
    const float* emb    = (const float*)d_in[1];
    const float* w_deep = (const float*)d_in[2];
    const float* b_deep = (const float*)d_in[3];
    const float* w_ffn  = (const float*)d_in[4];
    const float* b_ffn  = (const float*)d_in[5];
    float* out = (float*)d_out;

    deepfm_fused_kernel<<<8192, NTHREADS>>>(x, emb, w_deep, b_deep, w_ffn, b_ffn, out);
}

// round 3
// speedup vs baseline: 2.2036x; 2.2036x over previous
#include <cuda_runtime.h>
#include <cuda_bf16.h>

#define TS       100
#define FDIM     64
#define HDIM     32
#define NPAIR    4950
#define DEEP_N   3200            // TS * HDIM
#define WIDE_OFF 8150            // DEEP_N + NPAIR
#define NTHREADS 256

#define MT_FM    7               // m16 tiles covering 112 >= 100 rows
#define KT_FM    8               // k16 tiles covering 128 >= 100
#define NT_FM    8               // n8 tiles covering 64 cols
#define KT_DP    4               // k16 tiles covering 64
#define NT_DP    4               // n8 tiles covering 32

#define EB_STRIDE  72            // halves; bank-conflict-free for A-frag reads
#define EBT_STRIDE 136           // halves; bank-conflict-free for B-frag reads

// ---- batch-invariant fragment-major constants (built per launch, deterministic) ----
__device__ uint4 g_Afrag[MT_FM * KT_FM * 32];   // A_sym (w_fm/2) fragments, 28.7KB
__device__ uint2 g_wdfrag[KT_DP * NT_DP * 32];  // w_deep B fragments, 4KB

__device__ __forceinline__ unsigned pack_bf2(float lo, float hi) {
    __nv_bfloat162 h = __floats2bfloat162_rn(lo, hi);
    return *reinterpret_cast<unsigned*>(&h);
}

__global__ void build_consts(const float* __restrict__ w_deep,
                             const float* __restrict__ w_ffn)
{
    const int tid  = blockIdx.x * blockDim.x + threadIdx.x;
    const int lane = tid & 31;

    // A_sym fragments: A[i][j] = 0.5 * w_fm[tri(i,j)] for i!=j (i,j < TS), else 0
    if (tid < MT_FM * KT_FM * 32) {
        const int k = (tid >> 5) & 7;
        const int m = tid >> 8;
        unsigned r[4];
        #pragma unroll
        for (int j = 0; j < 4; ++j) {
            const int row = m * 16 + (lane >> 2) + (j & 1) * 8;
            const int c0  = k * 16 + (lane & 3) * 2 + (j >> 1) * 8;
            float v[2];
            #pragma unroll
            for (int q = 0; q < 2; ++q) {
                const int col = c0 + q;
                float a = 0.f;
                if (row < TS && col < TS && row != col) {
                    const int i = row < col ? row : col;
                    const int jj = row < col ? col : row;
                    const int idx = i * (2 * TS - i - 1) / 2 + (jj - i - 1);
                    a = 0.5f * w_ffn[DEEP_N + idx];
                }
                v[q] = a;
            }
            r[j] = pack_bf2(v[0], v[1]);
        }
        g_Afrag[tid] = make_uint4(r[0], r[1], r[2], r[3]);
    }

    // w_deep B fragments: B(k=f, n=h) = w_deep[f][h], w_deep row-major [64][32]
    if (tid < KT_DP * NT_DP * 32) {
        const int n = (tid >> 5) & 3;
        const int k = tid >> 7;
        unsigned r[2];
        #pragma unroll
        for (int j = 0; j < 2; ++j) {
            const int f0 = k * 16 + (lane & 3) * 2 + j * 8;
            const int h  = n * 8 + (lane >> 2);
            r[j] = pack_bf2(w_deep[f0 * HDIM + h], w_deep[(f0 + 1) * HDIM + h]);
        }
        g_wdfrag[tid] = make_uint2(r[0], r[1]);
    }
}

__device__ __forceinline__ void mma_bf16(float* c,
                                         unsigned a0, unsigned a1, unsigned a2, unsigned a3,
                                         unsigned b0, unsigned b1)
{
    asm volatile("mma.sync.aligned.m16n8k16.row.col.f32.bf16.bf16.f32 "
                 "{%0,%1,%2,%3}, {%4,%5,%6,%7}, {%8,%9}, {%0,%1,%2,%3};"
                 : "+f"(c[0]), "+f"(c[1]), "+f"(c[2]), "+f"(c[3])
                 : "r"(a0), "r"(a1), "r"(a2), "r"(a3), "r"(b0), "r"(b1));
}

__global__ __launch_bounds__(NTHREADS)
void deepfm_mma_kernel(const int* __restrict__ x,
                       const float* __restrict__ emb,
                       const float* __restrict__ b_deep,
                       const float* __restrict__ w_ffn,
                       const float* __restrict__ b_ffn,
                       float* __restrict__ out)
{
    __shared__ __align__(16) __nv_bfloat16 sEb[112 * EB_STRIDE];    // E row-major [t][f]
    __shared__ __align__(16) __nv_bfloat16 sEbT[64 * EBT_STRIDE];   // E^T [f][t]
    __shared__ int   tok[TS];
    __shared__ float red[NTHREADS / 32];

    const int b    = blockIdx.x;
    const int tid  = threadIdx.x;
    const int lane = tid & 31;
    const int wid  = tid >> 5;

    // ---- zero smem (pad regions must be 0), load tokens ----
    {
        uint4* z1 = reinterpret_cast<uint4*>(sEb);
        uint4* z2 = reinterpret_cast<uint4*>(sEbT);
        const int n1 = 112 * EB_STRIDE / 8, n2 = 64 * EBT_STRIDE / 8;
        for (int i = tid; i < n1; i += NTHREADS) z1[i] = make_uint4(0, 0, 0, 0);
        for (int i = tid; i < n2; i += NTHREADS) z2[i] = make_uint4(0, 0, 0, 0);
        if (tid < TS) tok[tid] = x[b * TS + tid];
    }
    __syncthreads();

    // ---- gather + convert: 50 t-pairs x 32 f-pairs ----
    for (int idx = tid; idx < 50 * 32; idx += NTHREADS) {
        const int t0 = (idx >> 5) * 2;
        const int f0 = (idx & 31) * 2;
        const float2 ea = *(const float2*)(emb + (long)tok[t0] * FDIM + f0);
        const float2 eb = *(const float2*)(emb + (long)tok[t0 + 1] * FDIM + f0);
        *(unsigned*)(sEb + t0 * EB_STRIDE + f0)        = pack_bf2(ea.x, ea.y);
        *(unsigned*)(sEb + (t0 + 1) * EB_STRIDE + f0)  = pack_bf2(eb.x, eb.y);
        *(unsigned*)(sEbT + f0 * EBT_STRIDE + t0)      = pack_bf2(ea.x, eb.x);
        *(unsigned*)(sEbT + (f0 + 1) * EBT_STRIDE + t0) = pack_bf2(ea.y, eb.y);
    }
    __syncthreads();

    float partial = 0.f;

    // ---- wide term (all threads): sum E[t][f] * w_wide[t*64+f] ----
    {
        const float* ww = w_ffn + WIDE_OFF;
        for (int i = tid; i < TS * FDIM / 2; i += NTHREADS) {
            const int t = i >> 5, f = (i & 31) * 2;
            const __nv_bfloat162 e2 = *(const __nv_bfloat162*)(sEb + t * EB_STRIDE + f);
            const float2 w2 = *(const float2*)(ww + t * FDIM + f);
            partial += __bfloat162float(e2.x) * w2.x + __bfloat162float(e2.y) * w2.y;
        }
    }

    if (wid < MT_FM) {
        // ---- fm: H = A_sym @ E for m-tile `wid`; fm = sum E .* H ----
        const int m = wid;
        float acc[NT_FM][4];
        #pragma unroll
        for (int n = 0; n < NT_FM; ++n)
            #pragma unroll
            for (int q = 0; q < 4; ++q) acc[n][q] = 0.f;

        const uint4* afp = g_Afrag + m * KT_FM * 32 + lane;
        const int brow = lane >> 2;          // within-tile n offset
        const int koff = (lane & 3) * 2;     // within-tile k offset

        #pragma unroll
        for (int k = 0; k < KT_FM; ++k) {
            const uint4 a = afp[k * 32];
            const __nv_bfloat16* bp = sEbT + k * 16 + koff;
            #pragma unroll
            for (int n = 0; n < NT_FM; ++n) {
                const __nv_bfloat16* bb = bp + (n * 8 + brow) * EBT_STRIDE;
                const unsigned b0 = *(const unsigned*)bb;
                const unsigned b1 = *(const unsigned*)(bb + 8);
                mma_bf16(acc[n], a.x, a.y, a.z, a.w, b0, b1);
            }
        }
        // epilogue: partial += acc .* E  (weights already folded into A)
        const int t0 = m * 16 + (lane >> 2);
        #pragma unroll
        for (int n = 0; n < NT_FM; ++n) {
            const int f = n * 8 + (lane & 3) * 2;
            const __nv_bfloat162 e0 = *(const __nv_bfloat162*)(sEb + t0 * EB_STRIDE + f);
            const __nv_bfloat162 e1 = *(const __nv_bfloat162*)(sEb + (t0 + 8) * EB_STRIDE + f);
            partial += acc[n][0] * __bfloat162float(e0.x) + acc[n][1] * __bfloat162float(e0.y);
            partial += acc[n][2] * __bfloat162float(e1.x) + acc[n][3] * __bfloat162float(e1.y);
        }
    } else {
        // ---- deep (warp 7): D = E @ w_deep, relu, dot with w_ffn ----
        const int r0 = lane >> 2;
        const int c0 = (lane & 3) * 2;
        for (int m = 0; m < MT_FM; ++m) {
            float acc[NT_DP][4];
            #pragma unroll
            for (int n = 0; n < NT_DP; ++n)
                #pragma unroll
                for (int q = 0; q < 4; ++q) acc[n][q] = 0.f;

            const __nv_bfloat16* arow0 = sEb + (m * 16 + r0) * EB_STRIDE;
            const __nv_bfloat16* arow1 = arow0 + 8 * EB_STRIDE;
            #pragma unroll
            for (int k = 0; k < KT_DP; ++k) {
                const int c = k * 16 + c0;
                const unsigned a0 = *(const unsigned*)(arow0 + c);
                const unsigned a1 = *(const unsigned*)(arow1 + c);
                const unsigned a2 = *(const unsigned*)(arow0 + c + 8);
                const unsigned a3 = *(const unsigned*)(arow1 + c + 8);
                const uint2* bfp = g_wdfrag + k * NT_DP * 32 + lane;
                #pragma unroll
                for (int n = 0; n < NT_DP; ++n) {
                    const uint2 bf = bfp[n * 32];
                    mma_bf16(acc[n], a0, a1, a2, a3, bf.x, bf.y);
                }
            }
            const int t0 = m * 16 + r0;
            const int t1 = t0 + 8;
            #pragma unroll
            for (int n = 0; n < NT_DP; ++n) {
                const int h = n * 8 + c0;
                const float2 bd = *(const float2*)(b_deep + h);
                if (t0 < TS) {
                    const float2 w = *(const float2*)(w_ffn + t0 * HDIM + h);
                    partial += fmaxf(acc[n][0] + bd.x, 0.f) * w.x
                             + fmaxf(acc[n][1] + bd.y, 0.f) * w.y;
                }
                if (t1 < TS) {
                    const float2 w = *(const float2*)(w_ffn + t1 * HDIM + h);
                    partial += fmaxf(acc[n][2] + bd.x, 0.f) * w.x
                             + fmaxf(acc[n][3] + bd.y, 0.f) * w.y;
                }
            }
        }
    }

    // ---- block reduce + sigmoid ----
    #pragma unroll
    for (int off = 16; off; off >>= 1)
        partial += __shfl_xor_sync(0xffffffffu, partial, off);
    if (lane == 0) red[wid] = partial;
    __syncthreads();
    if (tid == 0) {
        float total = 0.f;
        #pragma unroll
        for (int w = 0; w < NTHREADS / 32; ++w) total += red[w];
        total += b_ffn[0];
        out[b] = 1.f / (1.f + expf(-total));
    }
}

extern "C" void kernel_launch(void* const* d_in, const int* in_sizes, int n_in,
                              void* d_out, int out_size) {
    const int*   x      = (const int*)d_in[0];
    const float* emb    = (const float*)d_in[1];
    const float* w_deep = (const float*)d_in[2];
    const float* b_deep = (const float*)d_in[3];
    const float* w_ffn  = (const float*)d_in[4];
    const float* b_ffn  = (const float*)d_in[5];
    float* out = (float*)d_out;

    build_consts<<<7, 256>>>(w_deep, w_ffn);
    deepfm_mma_kernel<<<8192, NTHREADS>>>(x, emb, b_deep, w_ffn, b_ffn, out);
}

// round 4
// speedup vs baseline: 3.4912x; 1.5843x over previous
#include <cuda_runtime.h>
#include <cuda_bf16.h>

#define TS       100
#define FDIM     64
#define HDIM     32
#define DEEP_N   3200            // TS * HDIM
#define WIDE_OFF 8150            // DEEP_N + NPAIR(4950)
#define NTHREADS 256

#define MT    7                  // m16 tiles covering 112 >= 100 rows
#define KT    7                  // k16 tiles covering 112 >= 100 (fm)
#define NT    8                  // n8 tiles covering 64 (fm)
#define KT_DP 4                  // k16 tiles covering 64 (deep)
#define NT_DP 4                  // n8 tiles covering 32 (deep)

#define EB_STRIDE 72             // halves per row; 144B -> conflict-free ldmatrix

// ---- batch-invariant fragment-major constants (rebuilt each launch) ----
__device__ uint4  g_Afrag[MT * KT * 32];      // A_sym = w_fm/2, bf16 a-frags
__device__ float4 g_widefrag[MT * NT * 32];   // w_wide in fm C-frag layout
__device__ uint2  g_wdfrag[KT_DP * NT_DP * 32];  // w_deep bf16 b-frags
__device__ float4 g_wffnd[MT * NT_DP * 32];   // w_ffn(deep) in deep C-frag layout
__device__ float2 g_bdfrag[NT_DP * 32];       // b_deep in deep C-frag layout

__device__ __forceinline__ unsigned pack_bf2(float lo, float hi) {
    __nv_bfloat162 h = __floats2bfloat162_rn(lo, hi);
    return *reinterpret_cast<unsigned*>(&h);
}
__device__ __forceinline__ unsigned smem_u32(const void* p) {
    return (unsigned)__cvta_generic_to_shared(p);
}

__global__ void build_consts(const float* __restrict__ w_deep,
                             const float* __restrict__ b_deep,
                             const float* __restrict__ w_ffn)
{
    const int tid  = blockIdx.x * blockDim.x + threadIdx.x;
    const int lane = tid & 31;

    // A_sym a-fragments: A[i][j] = 0.5*w_fm[tri(i,j)] (i!=j, i,j<TS), else 0
    if (tid < MT * KT * 32) {
        const int k = (tid >> 5) % KT;
        const int m = tid / (KT * 32);
        unsigned r[4];
        #pragma unroll
        for (int j = 0; j < 4; ++j) {
            const int row = m * 16 + (lane >> 2) + (j & 1) * 8;
            const int c0  = k * 16 + (lane & 3) * 2 + (j >> 1) * 8;
            float v[2];
            #pragma unroll
            for (int q = 0; q < 2; ++q) {
                const int col = c0 + q;
                float a = 0.f;
                if (row < TS && col < TS && row != col) {
                    const int i  = row < col ? row : col;
                    const int jj = row < col ? col : row;
                    const int idx = i * (2 * TS - i - 1) / 2 + (jj - i - 1);
                    a = 0.5f * w_ffn[DEEP_N + idx];
                }
                v[q] = a;
            }
            r[j] = pack_bf2(v[0], v[1]);
        }
        g_Afrag[tid] = make_uint4(r[0], r[1], r[2], r[3]);
    }

    // w_wide in fm C-fragment layout (zero-padded beyond TS)
    if (tid < MT * NT * 32) {
        const int n = (tid >> 5) % NT;
        const int m = tid / (NT * 32);
        const int t0 = m * 16 + (lane >> 2);
        const int f  = n * 8 + (lane & 3) * 2;
        float4 w = make_float4(0.f, 0.f, 0.f, 0.f);
        if (t0 < TS) {
            w.x = w_ffn[WIDE_OFF + t0 * FDIM + f];
            w.y = w_ffn[WIDE_OFF + t0 * FDIM + f + 1];
        }
        if (t0 + 8 < TS) {
            w.z = w_ffn[WIDE_OFF + (t0 + 8) * FDIM + f];
            w.w = w_ffn[WIDE_OFF + (t0 + 8) * FDIM + f + 1];
        }
        g_widefrag[tid] = w;
    }

    // w_deep b-fragments
    if (tid < KT_DP * NT_DP * 32) {
        const int n = (tid >> 5) & 3;
        const int k = tid >> 7;
        unsigned r[2];
        #pragma unroll
        for (int j = 0; j < 2; ++j) {
            const int f0 = k * 16 + (lane & 3) * 2 + j * 8;
            const int h  = n * 8 + (lane >> 2);
            r[j] = pack_bf2(w_deep[f0 * HDIM + h], w_deep[(f0 + 1) * HDIM + h]);
        }
        g_wdfrag[tid] = make_uint2(r[0], r[1]);
    }

    // w_ffn(deep) in deep C-fragment layout (zero-padded beyond TS)
    if (tid < MT * NT_DP * 32) {
        const int n = (tid >> 5) % NT_DP;
        const int m = tid / (NT_DP * 32);
        const int t0 = m * 16 + (lane >> 2);
        const int h  = n * 8 + (lane & 3) * 2;
        float4 w = make_float4(0.f, 0.f, 0.f, 0.f);
        if (t0 < TS)     { w.x = w_ffn[t0 * HDIM + h];       w.y = w_ffn[t0 * HDIM + h + 1]; }
        if (t0 + 8 < TS) { w.z = w_ffn[(t0 + 8) * HDIM + h]; w.w = w_ffn[(t0 + 8) * HDIM + h + 1]; }
        g_wffnd[tid] = w;
    }

    // b_deep in deep C-fragment layout
    if (tid < NT_DP * 32) {
        const int n = tid >> 5;
        const int h = n * 8 + (lane & 3) * 2;
        g_bdfrag[tid] = make_float2(b_deep[h], b_deep[h + 1]);
    }
}

__device__ __forceinline__ void mma_bf16(float* c,
                                         unsigned a0, unsigned a1, unsigned a2, unsigned a3,
                                         unsigned b0, unsigned b1)
{
    asm volatile("mma.sync.aligned.m16n8k16.row.col.f32.bf16.bf16.f32 "
                 "{%0,%1,%2,%3}, {%4,%5,%6,%7}, {%8,%9}, {%0,%1,%2,%3};"
                 : "+f"(c[0]), "+f"(c[1]), "+f"(c[2]), "+f"(c[3])
                 : "r"(a0), "r"(a1), "r"(a2), "r"(a3), "r"(b0), "r"(b1));
}
__device__ __forceinline__ void ldsm_x4(unsigned& r0, unsigned& r1, unsigned& r2, unsigned& r3,
                                        unsigned addr)
{
    asm volatile("ldmatrix.sync.aligned.m8n8.x4.shared.b16 {%0,%1,%2,%3}, [%4];"
                 : "=r"(r0), "=r"(r1), "=r"(r2), "=r"(r3) : "r"(addr));
}
__device__ __forceinline__ void ldsm_x4_trans(unsigned& r0, unsigned& r1, unsigned& r2, unsigned& r3,
                                              unsigned addr)
{
    asm volatile("ldmatrix.sync.aligned.m8n8.x4.trans.shared.b16 {%0,%1,%2,%3}, [%4];"
                 : "=r"(r0), "=r"(r1), "=r"(r2), "=r"(r3) : "r"(addr));
}

__global__ __launch_bounds__(NTHREADS)
void deepfm_mma_kernel(const int* __restrict__ x,
                       const float* __restrict__ emb,
                       const float* __restrict__ b_ffn,
                       float* __restrict__ out)
{
    __shared__ __align__(16) __nv_bfloat16 sEb[112 * EB_STRIDE];  // 16.1 KB, rows=t, cols=f
    __shared__ int   tok[TS];
    __shared__ float red[NTHREADS / 32];

    const int b    = blockIdx.x;
    const int tid  = threadIdx.x;
    const int lane = tid & 31;
    const int wid  = tid >> 5;

    // ---- tokens + zero only the pad rows (100..111) ----
    if (tid < TS) tok[tid] = x[b * TS + tid];
    if (tid < 12 * 9) {
        const int r = 100 + tid / 9;
        const int q = tid % 9;
        *reinterpret_cast<uint4*>(sEb + r * EB_STRIDE + q * 8) = make_uint4(0, 0, 0, 0);
    }
    __syncthreads();

    // ---- gather + bf16 convert: 100 tokens x 16 float4-chunks ----
    for (int idx = tid; idx < TS * 16; idx += NTHREADS) {
        const int t  = idx >> 4;
        const int fq = idx & 15;
        const float4 v = *(const float4*)(emb + (long)tok[t] * FDIM + fq * 4);
        const unsigned p0 = pack_bf2(v.x, v.y);
        const unsigned p1 = pack_bf2(v.z, v.w);
        *reinterpret_cast<uint2*>(sEb + t * EB_STRIDE + fq * 4) = make_uint2(p0, p1);
    }
    __syncthreads();

    float partial = 0.f;

    // ldmatrix per-lane base: group g supplies rows of the (g&1)-th 8-row block,
    // at column block (g>>1)*8
    const int g = lane >> 3, r8 = lane & 7;
    const unsigned lds_base =
        smem_u32(sEb + ((g & 1) * 8 + r8) * EB_STRIDE + (g >> 1) * 8);

    if (wid < MT) {
        // ---- fm: H = A_sym @ E for m-tile `wid`; partial += (H + W_wide) .* E ----
        float acc[NT][4];
        #pragma unroll
        for (int n = 0; n < NT; ++n)
            #pragma unroll
            for (int q = 0; q < 4; ++q) acc[n][q] = 0.f;

        const uint4* afp = g_Afrag + wid * KT * 32 + lane;
        #pragma unroll
        for (int k = 0; k < KT; ++k) {
            const uint4 a = afp[k * 32];
            const unsigned rowB = lds_base + k * (16 * EB_STRIDE * 2);
            #pragma unroll
            for (int np = 0; np < 4; ++np) {
                unsigned b0, b1, b2, b3;
                ldsm_x4_trans(b0, b1, b2, b3, rowB + np * 32);
                mma_bf16(acc[2 * np],     a.x, a.y, a.z, a.w, b0, b1);
                mma_bf16(acc[2 * np + 1], a.x, a.y, a.z, a.w, b2, b3);
            }
        }
        // epilogue: wide term folded in via precomputed fragment weights
        const int t0 = wid * 16 + (lane >> 2);
        const __nv_bfloat16* e0p = sEb + t0 * EB_STRIDE + (lane & 3) * 2;
        const __nv_bfloat16* e1p = e0p + 8 * EB_STRIDE;
        const float4* wfp = g_widefrag + wid * NT * 32 + lane;
        #pragma unroll
        for (int n = 0; n < NT; ++n) {
            const float4 wf = wfp[n * 32];
            const __nv_bfloat162 e0 = *(const __nv_bfloat162*)(e0p + n * 8);
            const __nv_bfloat162 e1 = *(const __nv_bfloat162*)(e1p + n * 8);
            partial += (acc[n][0] + wf.x) * __bfloat162float(e0.x)
                     + (acc[n][1] + wf.y) * __bfloat162float(e0.y)
                     + (acc[n][2] + wf.z) * __bfloat162float(e1.x)
                     + (acc[n][3] + wf.w) * __bfloat162float(e1.y);
        }
    } else {
        // ---- deep (warp 7): D = E @ w_deep, relu, dot with w_ffn ----
        float2 bd[NT_DP];
        #pragma unroll
        for (int n = 0; n < NT_DP; ++n) bd[n] = g_bdfrag[n * 32 + lane];

        for (int m = 0; m < MT; ++m) {
            float acc[NT_DP][4];
            #pragma unroll
            for (int n = 0; n < NT_DP; ++n)
                #pragma unroll
                for (int q = 0; q < 4; ++q) acc[n][q] = 0.f;

            const unsigned rowA = lds_base + m * (16 * EB_STRIDE * 2);
            #pragma unroll
            for (int k = 0; k < KT_DP; ++k) {
                unsigned a0, a1, a2, a3;
                ldsm_x4(a0, a1, a2, a3, rowA + k * 32);
                const uint2* bfp = g_wdfrag + k * NT_DP * 32 + lane;
                #pragma unroll
                for (int n = 0; n < NT_DP; ++n) {
                    const uint2 bb = bfp[n * 32];
                    mma_bf16(acc[n], a0, a1, a2, a3, bb.x, bb.y);
                }
            }
            const float4* wfp = g_wffnd + m * NT_DP * 32 + lane;
            #pragma unroll
            for (int n = 0; n < NT_DP; ++n) {
                const float4 wf = wfp[n * 32];
                partial += fmaxf(acc[n][0] + bd[n].x, 0.f) * wf.x
                         + fmaxf(acc[n][1] + bd[n].y, 0.f) * wf.y
                         + fmaxf(acc[n][2] + bd[n].x, 0.f) * wf.z
                         + fmaxf(acc[n][3] + bd[n].y, 0.f) * wf.w;
            }
        }
    }

    // ---- block reduce + sigmoid ----
    #pragma unroll
    for (int off = 16; off; off >>= 1)
        partial += __shfl_xor_sync(0xffffffffu, partial, off);
    if (lane == 0) red[wid] = partial;
    __syncthreads();
    if (tid == 0) {
        float total = 0.f;
        #pragma unroll
        for (int w = 0; w < NTHREADS / 32; ++w) total += red[w];
        total += b_ffn[0];
        out[b] = 1.f / (1.f + expf(-total));
    }
}

extern "C" void kernel_launch(void* const* d_in, const int* in_sizes, int n_in,
                              void* d_out, int out_size) {
    const int*   x      = (const int*)d_in[0];
    const float* emb    = (const float*)d_in[1];
    const float* w_deep = (const float*)d_in[2];
    const float* b_deep = (const float*)d_in[3];
    const float* w_ffn  = (const float*)d_in[4];
    const float* b_ffn  = (const float*)d_in[5];
    float* out = (float*)d_out;

    build_consts<<<7, 256>>>(w_deep, b_deep, w_ffn);
    deepfm_mma_kernel<<<8192, NTHREADS>>>(x, emb, b_ffn, out);
}

// round 5
// speedup vs baseline: 4.4686x; 1.2800x over previous
#include <cuda_runtime.h>
#include <cuda_bf16.h>

#define TS       100
#define FDIM     64
#define HDIM     32
#define DEEP_N   3200            // TS * HDIM
#define WIDE_OFF 8150            // DEEP_N + NPAIR(4950)
#define NTHREADS 224
#define NWARPS   7

#define MT    7                  // m16 tiles covering 112 >= 100 rows
#define KT    7                  // k16 tiles covering 112 >= 100 (fm)
#define NT    8                  // n8 tiles covering 64 (fm)
#define KT_DP 4                  // k16 tiles covering 64 (deep)
#define NT_DP 4                  // n8 tiles covering 32 (deep)

#define EB_STRIDE 72             // halves per row; 144B -> conflict-free ldmatrix

// ---- batch-invariant fragment-major constants (rebuilt each launch) ----
__device__ uint4  g_Afrag[MT * KT * 32];      // A_sym = w_fm/2, bf16 a-frags
__device__ float4 g_widefrag[MT * NT * 32];   // w_wide in fm C-frag layout
__device__ uint2  g_wdfrag[KT_DP * NT_DP * 32];  // w_deep bf16 b-frags
__device__ float4 g_wffnd[MT * NT_DP * 32];   // w_ffn(deep) in deep C-frag layout
__device__ float2 g_bdfrag[NT_DP * 32];       // b_deep in deep C-frag layout

__device__ __forceinline__ unsigned pack_bf2(float lo, float hi) {
    __nv_bfloat162 h = __floats2bfloat162_rn(lo, hi);
    return *reinterpret_cast<unsigned*>(&h);
}
__device__ __forceinline__ unsigned smem_u32(const void* p) {
    return (unsigned)__cvta_generic_to_shared(p);
}

__global__ void build_consts(const float* __restrict__ w_deep,
                             const float* __restrict__ b_deep,
                             const float* __restrict__ w_ffn)
{
    const int tid  = blockIdx.x * blockDim.x + threadIdx.x;
    const int lane = tid & 31;

    // A_sym a-fragments: A[i][j] = 0.5*w_fm[tri(i,j)] (i!=j, i,j<TS), else 0
    if (tid < MT * KT * 32) {
        const int k = (tid >> 5) % KT;
        const int m = tid / (KT * 32);
        unsigned r[4];
        #pragma unroll
        for (int j = 0; j < 4; ++j) {
            const int row = m * 16 + (lane >> 2) + (j & 1) * 8;
            const int c0  = k * 16 + (lane & 3) * 2 + (j >> 1) * 8;
            float v[2];
            #pragma unroll
            for (int q = 0; q < 2; ++q) {
                const int col = c0 + q;
                float a = 0.f;
                if (row < TS && col < TS && row != col) {
                    const int i  = row < col ? row : col;
                    const int jj = row < col ? col : row;
                    const int idx = i * (2 * TS - i - 1) / 2 + (jj - i - 1);
                    a = 0.5f * w_ffn[DEEP_N + idx];
                }
                v[q] = a;
            }
            r[j] = pack_bf2(v[0], v[1]);
        }
        g_Afrag[tid] = make_uint4(r[0], r[1], r[2], r[3]);
    }

    // w_wide in fm C-fragment layout (zero-padded beyond TS)
    if (tid < MT * NT * 32) {
        const int n = (tid >> 5) % NT;
        const int m = tid / (NT * 32);
        const int t0 = m * 16 + (lane >> 2);
        const int f  = n * 8 + (lane & 3) * 2;
        float4 w = make_float4(0.f, 0.f, 0.f, 0.f);
        if (t0 < TS) {
            w.x = w_ffn[WIDE_OFF + t0 * FDIM + f];
            w.y = w_ffn[WIDE_OFF + t0 * FDIM + f + 1];
        }
        if (t0 + 8 < TS) {
            w.z = w_ffn[WIDE_OFF + (t0 + 8) * FDIM + f];
            w.w = w_ffn[WIDE_OFF + (t0 + 8) * FDIM + f + 1];
        }
        g_widefrag[tid] = w;
    }

    // w_deep b-fragments
    if (tid < KT_DP * NT_DP * 32) {
        const int n = (tid >> 5) & 3;
        const int k = tid >> 7;
        unsigned r[2];
        #pragma unroll
        for (int j = 0; j < 2; ++j) {
            const int f0 = k * 16 + (lane & 3) * 2 + j * 8;
            const int h  = n * 8 + (lane >> 2);
            r[j] = pack_bf2(w_deep[f0 * HDIM + h], w_deep[(f0 + 1) * HDIM + h]);
        }
        g_wdfrag[tid] = make_uint2(r[0], r[1]);
    }

    // w_ffn(deep) in deep C-fragment layout (zero-padded beyond TS)
    if (tid < MT * NT_DP * 32) {
        const int n = (tid >> 5) % NT_DP;
        const int m = tid / (NT_DP * 32);
        const int t0 = m * 16 + (lane >> 2);
        const int h  = n * 8 + (lane & 3) * 2;
        float4 w = make_float4(0.f, 0.f, 0.f, 0.f);
        if (t0 < TS)     { w.x = w_ffn[t0 * HDIM + h];       w.y = w_ffn[t0 * HDIM + h + 1]; }
        if (t0 + 8 < TS) { w.z = w_ffn[(t0 + 8) * HDIM + h]; w.w = w_ffn[(t0 + 8) * HDIM + h + 1]; }
        g_wffnd[tid] = w;
    }

    // b_deep in deep C-fragment layout
    if (tid < NT_DP * 32) {
        const int n = tid >> 5;
        const int h = n * 8 + (lane & 3) * 2;
        g_bdfrag[tid] = make_float2(b_deep[h], b_deep[h + 1]);
    }
}

__device__ __forceinline__ void mma_bf16(float* c,
                                         unsigned a0, unsigned a1, unsigned a2, unsigned a3,
                                         unsigned b0, unsigned b1)
{
    asm volatile("mma.sync.aligned.m16n8k16.row.col.f32.bf16.bf16.f32 "
                 "{%0,%1,%2,%3}, {%4,%5,%6,%7}, {%8,%9}, {%0,%1,%2,%3};"
                 : "+f"(c[0]), "+f"(c[1]), "+f"(c[2]), "+f"(c[3])
                 : "r"(a0), "r"(a1), "r"(a2), "r"(a3), "r"(b0), "r"(b1));
}
__device__ __forceinline__ void ldsm_x4(unsigned& r0, unsigned& r1, unsigned& r2, unsigned& r3,
                                        unsigned addr)
{
    asm volatile("ldmatrix.sync.aligned.m8n8.x4.shared.b16 {%0,%1,%2,%3}, [%4];"
                 : "=r"(r0), "=r"(r1), "=r"(r2), "=r"(r3) : "r"(addr));
}
__device__ __forceinline__ void ldsm_x4_trans(unsigned& r0, unsigned& r1, unsigned& r2, unsigned& r3,
                                              unsigned addr)
{
    asm volatile("ldmatrix.sync.aligned.m8n8.x4.trans.shared.b16 {%0,%1,%2,%3}, [%4];"
                 : "=r"(r0), "=r"(r1), "=r"(r2), "=r"(r3) : "r"(addr));
}

__global__ __launch_bounds__(NTHREADS, 4)
void deepfm_mma_kernel(const int* __restrict__ x,
                       const float* __restrict__ emb,
                       const float* __restrict__ b_ffn,
                       float* __restrict__ out)
{
    __shared__ __align__(16) __nv_bfloat16 sEb[112 * EB_STRIDE];  // 16.1 KB, rows=t, cols=f
    __shared__ int   tok[TS];
    __shared__ float red[NWARPS];

    const int b    = blockIdx.x;
    const int tid  = threadIdx.x;
    const int lane = tid & 31;
    const int wid  = tid >> 5;

    // ---- tokens + zero only the pad rows (100..111) ----
    if (tid < TS) tok[tid] = x[b * TS + tid];
    if (tid < 12 * 9) {
        const int r = 100 + tid / 9;
        const int q = tid % 9;
        *reinterpret_cast<uint4*>(sEb + r * EB_STRIDE + q * 8) = make_uint4(0, 0, 0, 0);
    }
    __syncthreads();

    // ---- gather + bf16 convert: 100 tokens x 16 float4-chunks ----
    for (int idx = tid; idx < TS * 16; idx += NTHREADS) {
        const int t  = idx >> 4;
        const int fq = idx & 15;
        const float4 v = *(const float4*)(emb + (long)tok[t] * FDIM + fq * 4);
        const unsigned p0 = pack_bf2(v.x, v.y);
        const unsigned p1 = pack_bf2(v.z, v.w);
        *reinterpret_cast<uint2*>(sEb + t * EB_STRIDE + fq * 4) = make_uint2(p0, p1);
    }
    __syncthreads();

    float partial = 0.f;

    // ldmatrix per-lane base: group g supplies rows of the (g&1)-th 8-row block,
    // at column block (g>>1)*8
    const int g = lane >> 3, r8 = lane & 7;
    const unsigned lds_base =
        smem_u32(sEb + ((g & 1) * 8 + r8) * EB_STRIDE + (g >> 1) * 8);
    const unsigned rowM = lds_base + wid * (16 * EB_STRIDE * 2);

    // ================= deep for m-tile `wid` (16 MMAs) =================
    {
        float acc[NT_DP][4];
        #pragma unroll
        for (int n = 0; n < NT_DP; ++n)
            #pragma unroll
            for (int q = 0; q < 4; ++q) acc[n][q] = 0.f;

        #pragma unroll
        for (int k = 0; k < KT_DP; ++k) {
            unsigned a0, a1, a2, a3;
            ldsm_x4(a0, a1, a2, a3, rowM + k * 32);
            const uint2* bfp = g_wdfrag + k * NT_DP * 32 + lane;
            #pragma unroll
            for (int n = 0; n < NT_DP; ++n) {
                const uint2 bb = bfp[n * 32];
                mma_bf16(acc[n], a0, a1, a2, a3, bb.x, bb.y);
            }
        }
        const float4* wfp = g_wffnd + wid * NT_DP * 32 + lane;
        #pragma unroll
        for (int n = 0; n < NT_DP; ++n) {
            const float2 bd = g_bdfrag[n * 32 + lane];
            const float4 wf = wfp[n * 32];
            partial += fmaxf(acc[n][0] + bd.x, 0.f) * wf.x
                     + fmaxf(acc[n][1] + bd.y, 0.f) * wf.y
                     + fmaxf(acc[n][2] + bd.x, 0.f) * wf.z
                     + fmaxf(acc[n][3] + bd.y, 0.f) * wf.w;
        }
    }

    // ================= fm for m-tile `wid` (56 MMAs) =================
    {
        float acc[NT][4];
        #pragma unroll
        for (int n = 0; n < NT; ++n)
            #pragma unroll
            for (int q = 0; q < 4; ++q) acc[n][q] = 0.f;

        const uint4* afp = g_Afrag + wid * KT * 32 + lane;
        #pragma unroll
        for (int k = 0; k < KT; ++k) {
            const uint4 a = afp[k * 32];
            const unsigned rowB = lds_base + k * (16 * EB_STRIDE * 2);
            #pragma unroll
            for (int np = 0; np < 4; ++np) {
                unsigned b0, b1, b2, b3;
                ldsm_x4_trans(b0, b1, b2, b3, rowB + np * 32);
                mma_bf16(acc[2 * np],     a.x, a.y, a.z, a.w, b0, b1);
                mma_bf16(acc[2 * np + 1], a.x, a.y, a.z, a.w, b2, b3);
            }
        }
        // epilogue: wide term folded in via precomputed fragment weights
        const int t0 = wid * 16 + (lane >> 2);
        const __nv_bfloat16* e0p = sEb + t0 * EB_STRIDE + (lane & 3) * 2;
        const __nv_bfloat16* e1p = e0p + 8 * EB_STRIDE;
        const float4* wfp = g_widefrag + wid * NT * 32 + lane;
        #pragma unroll
        for (int n = 0; n < NT; ++n) {
            const float4 wf = wfp[n * 32];
            const __nv_bfloat162 e0 = *(const __nv_bfloat162*)(e0p + n * 8);
            const __nv_bfloat162 e1 = *(const __nv_bfloat162*)(e1p + n * 8);
            partial += (acc[n][0] + wf.x) * __bfloat162float(e0.x)
                     + (acc[n][1] + wf.y) * __bfloat162float(e0.y)
                     + (acc[n][2] + wf.z) * __bfloat162float(e1.x)
                     + (acc[n][3] + wf.w) * __bfloat162float(e1.y);
        }
    }

    // ---- block reduce + sigmoid ----
    #pragma unroll
    for (int off = 16; off; off >>= 1)
        partial += __shfl_xor_sync(0xffffffffu, partial, off);
    if (lane == 0) red[wid] = partial;
    __syncthreads();
    if (tid == 0) {
        float total = 0.f;
        #pragma unroll
        for (int w = 0; w < NWARPS; ++w) total += red[w];
        total += b_ffn[0];
        out[b] = 1.f / (1.f + expf(-total));
    }
}

extern "C" void kernel_launch(void* const* d_in, const int* in_sizes, int n_in,
                              void* d_out, int out_size) {
    const int*   x      = (const int*)d_in[0];
    const float* emb    = (const float*)d_in[1];
    const float* w_deep = (const float*)d_in[2];
    const float* b_deep = (const float*)d_in[3];
    const float* w_ffn  = (const float*)d_in[4];
    const float* b_ffn  = (const float*)d_in[5];
    float* out = (float*)d_out;

    build_consts<<<7, 256>>>(w_deep, b_deep, w_ffn);
    deepfm_mma_kernel<<<8192, NTHREADS>>>(x, emb, b_ffn, out);
}

// round 7
// speedup vs baseline: 5.1218x; 1.1462x over previous
#include <cuda_runtime.h>
#include <cuda_bf16.h>

#define TS       100
#define FDIM     64
#define HDIM     32
#define DEEP_N   3200            // TS * HDIM
#define WIDE_OFF 8150            // DEEP_N + NPAIR(4950)
#define NTHREADS 224
#define NWARPS   7

#define MT    7                  // m16 tiles covering 112 >= 100 rows
#define KT_FM 4                  // k16 tiles over f (Gram: k = feature dim)
#define NBLK  28                 // upper-tri 16x16 S-blocks (7*8/2)
#define KT_DP 4                  // k16 tiles covering 64 (deep)
#define NT_DP 4                  // n8 tiles covering 32 (deep)

#define EB_STRIDE 72             // halves per row; 144B -> conflict-free ldmatrix

// ---- batch-invariant fragment-major constants (rebuilt each launch) ----
__device__ float4 g_wpair[NBLK * 2 * 32];        // pair weights, S C-frag layout
__device__ uint2  g_wdfrag[KT_DP * NT_DP * 32];  // w_deep bf16 b-frags
__device__ float4 g_wffnd[MT * NT_DP * 32];      // w_ffn(deep) in deep C-frag layout
__device__ float2 g_bdfrag[NT_DP * 32];          // b_deep in deep C-frag layout
__device__ __align__(16) float g_wwide[TS * FDIM];  // wide weights, 16B-aligned copy

__constant__ int DEEP_CNT[NWARPS]   = {0, 0, 1, 1, 1, 2, 2};
__constant__ int DEEP_START[NWARPS] = {0, 0, 0, 1, 2, 3, 5};

__device__ __forceinline__ unsigned pack_bf2(float lo, float hi) {
    __nv_bfloat162 h = __floats2bfloat162_rn(lo, hi);
    return *reinterpret_cast<unsigned*>(&h);
}
__device__ __forceinline__ unsigned smem_u32(const void* p) {
    return (unsigned)__cvta_generic_to_shared(p);
}
__device__ __forceinline__ float pairw(const float* w_ffn, int t, int tp) {
    if (t < TS && tp < TS && t < tp)
        return w_ffn[DEEP_N + t * (2 * TS - t - 1) / 2 + (tp - t - 1)];
    return 0.f;
}

__global__ void build_consts(const float* __restrict__ w_deep,
                             const float* __restrict__ b_deep,
                             const float* __restrict__ w_ffn)
{
    const int tid  = blockIdx.x * blockDim.x + threadIdx.x;
    const int lane = tid & 31;

    // aligned copy of wide weights (source only float2-aligned: 8150 % 4 == 2)
    if (tid < TS * FDIM / 2) {
        const float2 v = *(const float2*)(w_ffn + WIDE_OFF + tid * 2);
        *(float2*)(g_wwide + tid * 2) = v;
    }

    // pair-weight fragments for S = E E^T blocks (upper-tri, incl. diagonal)
    if (tid < NBLK * 2 * 32) {
        const int n   = (tid >> 5) & 1;
        const int blk = tid >> 6;
        // blk -> (mi, mj), mi <= mj, row-major over the triangle
        int mi = 0, rem = blk;
        while (rem >= MT - mi) { rem -= MT - mi; ++mi; }
        const int mj = mi + rem;
        const int t  = mi * 16 + (lane >> 2);
        const int tp = mj * 16 + n * 8 + (lane & 3) * 2;
        float4 w;
        w.x = pairw(w_ffn, t,     tp);
        w.y = pairw(w_ffn, t,     tp + 1);
        w.z = pairw(w_ffn, t + 8, tp);
        w.w = pairw(w_ffn, t + 8, tp + 1);
        g_wpair[tid] = w;
    }

    // w_deep b-fragments
    if (tid < KT_DP * NT_DP * 32) {
        const int n = (tid >> 5) & 3;
        const int k = tid >> 7;
        unsigned r[2];
        #pragma unroll
        for (int j = 0; j < 2; ++j) {
            const int f0 = k * 16 + (lane & 3) * 2 + j * 8;
            const int h  = n * 8 + (lane >> 2);
            r[j] = pack_bf2(w_deep[f0 * HDIM + h], w_deep[(f0 + 1) * HDIM + h]);
        }
        g_wdfrag[tid] = make_uint2(r[0], r[1]);
    }

    // w_ffn(deep) in deep C-fragment layout (zero-padded beyond TS)
    if (tid < MT * NT_DP * 32) {
        const int n = (tid >> 5) % NT_DP;
        const int m = tid / (NT_DP * 32);
        const int t0 = m * 16 + (lane >> 2);
        const int h  = n * 8 + (lane & 3) * 2;
        float4 w = make_float4(0.f, 0.f, 0.f, 0.f);
        if (t0 < TS)     { w.x = w_ffn[t0 * HDIM + h];       w.y = w_ffn[t0 * HDIM + h + 1]; }
        if (t0 + 8 < TS) { w.z = w_ffn[(t0 + 8) * HDIM + h]; w.w = w_ffn[(t0 + 8) * HDIM + h + 1]; }
        g_wffnd[tid] = w;
    }

    // b_deep in deep C-fragment layout
    if (tid < NT_DP * 32) {
        const int n = tid >> 5;
        const int h = n * 8 + (lane & 3) * 2;
        g_bdfrag[tid] = make_float2(b_deep[h], b_deep[h + 1]);
    }
}

__device__ __forceinline__ void mma_bf16(float* c,
                                         unsigned a0, unsigned a1, unsigned a2, unsigned a3,
                                         unsigned b0, unsigned b1)
{
    asm volatile("mma.sync.aligned.m16n8k16.row.col.f32.bf16.bf16.f32 "
                 "{%0,%1,%2,%3}, {%4,%5,%6,%7}, {%8,%9}, {%0,%1,%2,%3};"
                 : "+f"(c[0]), "+f"(c[1]), "+f"(c[2]), "+f"(c[3])
                 : "r"(a0), "r"(a1), "r"(a2), "r"(a3), "r"(b0), "r"(b1));
}
__device__ __forceinline__ void ldsm_x4(unsigned& r0, unsigned& r1, unsigned& r2, unsigned& r3,
                                        unsigned addr)
{
    asm volatile("ldmatrix.sync.aligned.m8n8.x4.shared.b16 {%0,%1,%2,%3}, [%4];"
                 : "=r"(r0), "=r"(r1), "=r"(r2), "=r"(r3) : "r"(addr));
}

__global__ __launch_bounds__(NTHREADS, 4)
void deepfm_mma_kernel(const int* __restrict__ x,
                       const float* __restrict__ emb,
                       const float* __restrict__ b_ffn,
                       float* __restrict__ out)
{
    __shared__ __align__(16) __nv_bfloat16 sEb[112 * EB_STRIDE];  // 16.1 KB, rows=t, cols=f
    __shared__ int   tok[TS];
    __shared__ float red[NWARPS];

    const int b    = blockIdx.x;
    const int tid  = threadIdx.x;
    const int lane = tid & 31;
    const int wid  = tid >> 5;

    // ---- tokens + zero only the pad rows (100..111) ----
    if (tid < TS) tok[tid] = x[b * TS + tid];
    if (tid < 12 * 9) {
        const int r = 100 + tid / 9;
        const int q = tid % 9;
        *reinterpret_cast<uint4*>(sEb + r * EB_STRIDE + q * 8) = make_uint4(0, 0, 0, 0);
    }
    __syncthreads();

    float partial = 0.f;

    // ---- gather + bf16 convert + WIDE term (fp32, from registers) ----
    for (int idx = tid; idx < TS * 16; idx += NTHREADS) {
        const int t  = idx >> 4;
        const int fq = idx & 15;
        const float4 v  = *(const float4*)(emb + (long)tok[t] * FDIM + fq * 4);
        const float4 wv = *(const float4*)(g_wwide + idx * 4);
        partial += v.x * wv.x + v.y * wv.y + v.z * wv.z + v.w * wv.w;
        const unsigned p0 = pack_bf2(v.x, v.y);
        const unsigned p1 = pack_bf2(v.z, v.w);
        *reinterpret_cast<uint2*>(sEb + t * EB_STRIDE + fq * 4) = make_uint2(p0, p1);
    }
    __syncthreads();

    // ldmatrix bases (g = lane>>3 selects 8x8 sub-matrix role)
    const int g = lane >> 3, r8 = lane & 7;
    // A-operand: mats [m0k0, m8k0, m0k8, m8k8]
    const unsigned ldsA =
        smem_u32(sEb + ((g & 1) * 8 + r8) * EB_STRIDE + (g >> 1) * 8);
    // B-operand: mats [n0k0, n0k8, n8k0, n8k8]
    const unsigned ldsB =
        smem_u32(sEb + ((g >> 1) * 8 + r8) * EB_STRIDE + (g & 1) * 8);
    const unsigned MROW = 16 * EB_STRIDE * 2;  // bytes per 16-row tile

    // ================= fm: S = E E^T, upper-tri blocks of row `wid` =================
    {
        // cache A-fragments for m-tile `wid` (all 4 k-tiles)
        uint4 ak[KT_FM];
        #pragma unroll
        for (int k = 0; k < KT_FM; ++k)
            ldsm_x4(ak[k].x, ak[k].y, ak[k].z, ak[k].w, ldsA + wid * MROW + k * 32);

        const int base = wid * MT - (wid * (wid - 1)) / 2;  // triangle row prefix
        for (int mj = wid; mj < MT; ++mj) {
            float acc[2][4];
            #pragma unroll
            for (int n = 0; n < 2; ++n)
                #pragma unroll
                for (int q = 0; q < 4; ++q) acc[n][q] = 0.f;

            #pragma unroll
            for (int k = 0; k < KT_FM; ++k) {
                unsigned b0, b1, b2, b3;
                ldsm_x4(b0, b1, b2, b3, ldsB + mj * MROW + k * 32);
                mma_bf16(acc[0], ak[k].x, ak[k].y, ak[k].z, ak[k].w, b0, b1);
                mma_bf16(acc[1], ak[k].x, ak[k].y, ak[k].z, ak[k].w, b2, b3);
            }
            const float4* wp = g_wpair + (base + mj - wid) * 64 + lane;
            const float4 w0 = wp[0];
            const float4 w1 = wp[32];
            partial += acc[0][0] * w0.x + acc[0][1] * w0.y
                     + acc[0][2] * w0.z + acc[0][3] * w0.w
                     + acc[1][0] * w1.x + acc[1][1] * w1.y
                     + acc[1][2] * w1.z + acc[1][3] * w1.w;
        }
    }

    // ================= deep: assigned m-tiles (inverse-balanced) =================
    {
        const int cnt = DEEP_CNT[wid];
        const int st  = DEEP_START[wid];
        for (int q = 0; q < cnt; ++q) {
            const int d = st + q;
            float acc[NT_DP][4];
            #pragma unroll
            for (int n = 0; n < NT_DP; ++n)
                #pragma unroll
                for (int p = 0; p < 4; ++p) acc[n][p] = 0.f;

            const unsigned rowA = ldsA + d * MROW;
            #pragma unroll
            for (int k = 0; k < KT_DP; ++k) {
                unsigned a0, a1, a2, a3;
                ldsm_x4(a0, a1, a2, a3, rowA + k * 32);
                const uint2* bfp = g_wdfrag + k * NT_DP * 32 + lane;
                #pragma unroll
                for (int n = 0; n < NT_DP; ++n) {
                    const uint2 bb = bfp[n * 32];
                    mma_bf16(acc[n], a0, a1, a2, a3, bb.x, bb.y);
                }
            }
            const float4* wfp = g_wffnd + d * NT_DP * 32 + lane;
            #pragma unroll
            for (int n = 0; n < NT_DP; ++n) {
                const float2 bd = g_bdfrag[n * 32 + lane];
                const float4 wf = wfp[n * 32];
                partial += fmaxf(acc[n][0] + bd.x, 0.f) * wf.x
                         + fmaxf(acc[n][1] + bd.y, 0.f) * wf.y
                         + fmaxf(acc[n][2] + bd.x, 0.f) * wf.z
                         + fmaxf(acc[n][3] + bd.y, 0.f) * wf.w;
            }
        }
    }

    // ---- block reduce + sigmoid ----
    #pragma unroll
    for (int off = 16; off; off >>= 1)
        partial += __shfl_xor_sync(0xffffffffu, partial, off);
    if (lane == 0) red[wid] = partial;
    __syncthreads();
    if (tid == 0) {
        float total = 0.f;
        #pragma unroll
        for (int w = 0; w < NWARPS; ++w) total += red[w];
        total += b_ffn[0];
        out[b] = 1.f / (1.f + expf(-total));
    }
}

extern "C" void kernel_launch(void* const* d_in, const int* in_sizes, int n_in,
                              void* d_out, int out_size) {
    const int*   x      = (const int*)d_in[0];
    const float* emb    = (const float*)d_in[1];
    const float* w_deep = (const float*)d_in[2];
    const float* b_deep = (const float*)d_in[3];
    const float* w_ffn  = (const float*)d_in[4];
    const float* b_ffn  = (const float*)d_in[5];
    float* out = (float*)d_out;

    build_consts<<<13, 256>>>(w_deep, b_deep, w_ffn);
    deepfm_mma_kernel<<<8192, NTHREADS>>>(x, emb, b_ffn, out);
}